// round 16
// baseline (speedup 1.0000x reference)
#include <cuda_runtime.h>
#include <cstdint>

#define KK 24
#define TT 512
#define BATCH 2048

// fused final-reduction state (self-resetting -> deterministic across replays)
__device__ double g_sum;
__device__ unsigned int g_ticket;

typedef unsigned int u32;
typedef unsigned short u16;

// ---- bf16x2 helpers ----
static __device__ __forceinline__ u32 bffma2(u32 a, u32 b, u32 c) {
    u32 d;
    asm("fma.rn.bf16x2 %0, %1, %2, %3;" : "=r"(d) : "r"(a), "r"(b), "r"(c));
    return d;
}
static __device__ __forceinline__ u32 bfmul2(u32 a, u32 b) {
    u32 d;
    asm("mul.rn.bf16x2 %0, %1, %2;" : "=r"(d) : "r"(a), "r"(b));
    return d;
}
static __device__ __forceinline__ u32 bfadd2(u32 a, u32 b) {
    u32 d;
    asm("add.rn.bf16x2 %0, %1, %2;" : "=r"(d) : "r"(a), "r"(b));
    return d;
}
static __device__ __forceinline__ u32 bfmax2(u32 a, u32 b) {
    u32 d;
    asm("max.bf16x2 %0, %1, %2;" : "=r"(d) : "r"(a), "r"(b));
    return d;
}
static __device__ __forceinline__ void bf2f(u32 v, float& lo, float& hi) {
    u16 l, h;
    asm("mov.b32 {%0, %1}, %2;" : "=h"(l), "=h"(h) : "r"(v));
    asm("cvt.f32.bf16 %0, %1;" : "=f"(lo) : "h"(l));
    asm("cvt.f32.bf16 %0, %1;" : "=f"(hi) : "h"(h));
}
static __device__ __forceinline__ u16 f2bf(float f) {
    u16 h;
    asm("cvt.rn.bf16.f32 %0, %1;" : "=h"(h) : "f"(f));
    return h;
}
// pack (lo, hi) floats -> bf16x2 (PTX: first src -> high half)
static __device__ __forceinline__ u32 pkbf(float lo, float hi) {
    u32 r;
    asm("cvt.rn.bf16x2.f32 %0, %1, %2;" : "=r"(r) : "f"(hi), "f"(lo));
    return r;
}
static __device__ __forceinline__ u32 swap16(u32 v) {
    u32 r;
    asm("prmt.b32 %0, %1, %1, 0x1032;" : "=r"(r) : "r"(v));
    return r;
}
static __device__ __forceinline__ u32 prmt(u32 a, u32 b, u32 sel) {
    u32 d;
    asm("prmt.b32 %0, %1, %2, %3;" : "=r"(d) : "r"(a), "r"(b), "r"(sel));
    return d;
}

// one recursion step, ONE batch, all-register exchange via shuffles.
// vq on entry: lane j holds (v_j, v_j) duplicated bf16x2; same on exit.
template <bool RN>
static __device__ __forceinline__ void step1(u32& vq, u32 psel,
                                             const u32* __restrict__ E2,
                                             u32 fe2, float& s) {
    // build packed pair (v_2p, v_2p+1), p = lane>>1, in every lane
    u32 oth = __shfl_xor_sync(0xffffffffu, vq, 1);
    u32 pair = prmt(vq, oth, psel);
    // broadcast the 12 pairs from even lanes 0,2,...,22
    u32 q0 = __shfl_sync(0xffffffffu, pair, 0);
    u32 q1 = __shfl_sync(0xffffffffu, pair, 2);
    u32 q2 = __shfl_sync(0xffffffffu, pair, 4);
    u32 q3 = __shfl_sync(0xffffffffu, pair, 6);
    u32 q4 = __shfl_sync(0xffffffffu, pair, 8);
    u32 q5 = __shfl_sync(0xffffffffu, pair, 10);
    u32 q6 = __shfl_sync(0xffffffffu, pair, 12);
    u32 q7 = __shfl_sync(0xffffffffu, pair, 14);
    u32 q8 = __shfl_sync(0xffffffffu, pair, 16);
    u32 q9 = __shfl_sync(0xffffffffu, pair, 18);
    u32 q10 = __shfl_sync(0xffffffffu, pair, 20);
    u32 q11 = __shfl_sync(0xffffffffu, pair, 22);

    u32 c0 = bfmul2(E2[0], q0);
    u32 c1 = bfmul2(E2[1], q1);
    u32 c2 = bfmul2(E2[2], q2);
    u32 c3 = bfmul2(E2[3], q3);
    c0 = bffma2(E2[4], q4, c0);
    c1 = bffma2(E2[5], q5, c1);
    c2 = bffma2(E2[6], q6, c2);
    c3 = bffma2(E2[7], q7, c3);
    c0 = bffma2(E2[8], q8, c0);
    c1 = bffma2(E2[9], q9, c1);
    c2 = bffma2(E2[10], q10, c2);
    c3 = bffma2(E2[11], q11, c3);
    u32 ct = bfadd2(bfadd2(c0, c1), bfadd2(c2, c3));
    u32 tot = bfadd2(ct, swap16(ct));  // both halves = d0+d1 (duplicated)
    vq = bfmul2(tot, fe2);

    if (RN) {
        // renorm by max of previous vector (lane-uniform)
        u32 m0 = bfmax2(q0, q1), m1 = bfmax2(q2, q3), m2 = bfmax2(q4, q5);
        u32 m3 = bfmax2(q6, q7), m4 = bfmax2(q8, q9), m5 = bfmax2(q10, q11);
        m0 = bfmax2(bfmax2(m0, m1), bfmax2(m2, m3));
        m0 = bfmax2(m0, bfmax2(m4, m5));
        float ma, mb;
        bf2f(m0, ma, mb);
        float m = fmaxf(ma, mb);
        float inv = 1.0f / m;
        vq = bfmul2(vq, pkbf(inv, inv));
        s += __logf(m);
    }
}

#define STEP(RN, IDX) step1<RN>(vq, psel, E2, fe2[IDX], s)

#define WIN8(RN0)          \
    STEP(RN0, 0);          \
    STEP(false, 1);        \
    STEP(false, 2);        \
    STEP(false, 3);        \
    STEP(false, 4);        \
    STEP(false, 5);        \
    STEP(false, 6);        \
    STEP(false, 7)

__global__ __launch_bounds__(64, 14) void crf_kernel(const float* __restrict__ feats,
                                                     const float* __restrict__ trans,
                                                     const void* __restrict__ tags,
                                                     const int* __restrict__ startp,
                                                     float* __restrict__ out) {
    __shared__ u16 vfin[2][32];  // final alpha / beta vectors (cross-warp handoff)
    __shared__ float sc_sh;      // backward warp's scale sum
    __shared__ float gold_sh;    // backward warp's gold partial
    const int lane = threadIdx.x & 31;
    const int w = threadIdx.x >> 5;  // 0 = forward, 1 = backward
    const int b = blockIdx.x;
    const int j = (lane < KK) ? lane : (KK - 1);
    const u32 psel = (lane & 1) ? 0x1054u : 0x5410u;  // pair-pack selector

    const int start = startp[0];  // low word valid for LE int32/int64

    // E2: fwd = row j of exp(trans), paired over i; bwd = column j (E^T)
    u32 E2[12];
    if (w == 0) {
#pragma unroll
        for (int k = 0; k < 12; ++k)
            E2[k] = pkbf(__expf(trans[j * KK + 2 * k]), __expf(trans[j * KK + 2 * k + 1]));
    } else {
#pragma unroll
        for (int k = 0; k < 12; ++k)
            E2[k] = pkbf(__expf(trans[(2 * k) * KK + j]), __expf(trans[(2 * k + 1) * KK + j]));
    }

    float s = 0.0f;
    u32 vq;
    const float* fb = feats + b * (TT * KK) + j;
    float fn[8];
    u32 fe2[8];

    if (w == 0) {
        // ---------------- forward: alpha, t = 1..256 (32 windows of 8) ----------------
        vq = (lane == start) ? 0x3F803F80u : 0u;  // dup bf16 1.0 at start label
#pragma unroll
        for (int r = 0; r < 8; ++r) fn[r] = __ldg(fb + (1 + r) * KK);
        {
#pragma unroll
            for (int r = 0; r < 8; ++r) {
                float e = __expf(fn[r]);
                fe2[r] = pkbf(e, e);
            }
            const float* p = fb + 9 * KK;
#pragma unroll
            for (int r = 0; r < 8; ++r) fn[r] = __ldg(p + r * KK);
            WIN8(false);
        }
#pragma unroll 1
        for (int wi = 1; wi < 32; ++wi) {
#pragma unroll
            for (int r = 0; r < 8; ++r) {
                float e = __expf(fn[r]);
                fe2[r] = pkbf(e, e);
            }
            const float* p = fb + (8 * (wi + 1) + 1) * KK;  // max base 257: in-bounds
#pragma unroll
            for (int r = 0; r < 8; ++r) fn[r] = __ldg(p + r * KK);
            WIN8(true);
        }
        vfin[0][lane] = (u16)vq;  // alpha(256)
    } else {
        // -------- backward: s(t)=fe_t*beta(t), t = 511..257, then beta(256) ----------
#pragma unroll
        for (int r = 0; r < 7; ++r) fn[r] = __ldg(fb + (511 - r) * KK);
        float e0 = __expf(fn[0]);
#pragma unroll
        for (int r = 0; r < 7; ++r) {
            float e = (r == 0) ? e0 : __expf(fn[r]);
            fe2[r] = pkbf(e, e);
        }
        vq = (lane < KK) ? (u32)(((u32)f2bf(e0) << 16) | (u32)f2bf(e0)) : 0u;  // s(511) dup
#pragma unroll
        for (int r = 0; r < 8; ++r) fn[r] = __ldg(fb + (504 - r) * KK);
        // prologue: t = 510..505
        STEP(false, 1);
        STEP(false, 2);
        STEP(false, 3);
        STEP(false, 4);
        STEP(false, 5);
        STEP(false, 6);
        // 31 windows of 8: t = 504..257
#pragma unroll 1
        for (int wi = 0; wi < 31; ++wi) {
#pragma unroll
            for (int r = 0; r < 8; ++r) {
                float e = __expf(fn[r]);
                fe2[r] = pkbf(e, e);
            }
            const float* p = fb + (504 - 8 * (wi + 1)) * KK;  // min base 256: in-bounds
#pragma unroll
            for (int r = 0; r < 8; ++r) fn[r] = __ldg(p + r * KK);
            WIN8(true);
        }
        // final fe-free step: beta(256) = E^T s(257)
        step1<false>(vq, psel, E2, 0x3F803F80u /* (1,1) */, s);
        if (lane == 0) sc_sh = s;
        vfin[1][lane] = (u16)vq;  // beta(256)
    }

    // ---- gold score: warps split the t-range of batch b (exact fp32) ----
    const u32* wds = (const u32*)tags;
    u32 hiw = wds[2 * lane + 1];
    const int is64 = (__ballot_sync(0xffffffffu, hiw != 0u) == 0u);
    float g = 0.0f;
    if (is64) {
        const long long* tg = (const long long*)tags + b * TT;
#pragma unroll
        for (int t = 1 + lane + 32 * w; t < TT; t += 64) {
            int it = (int)tg[t], ip = (int)tg[t - 1];
            g += trans[it * KK + ip] + __ldg(feats + (b * TT + t) * KK + it);
        }
    } else {
        const int* tg = (const int*)tags + b * TT;
#pragma unroll
        for (int t = 1 + lane + 32 * w; t < TT; t += 64) {
            int it = tg[t], ip = tg[t - 1];
            g += trans[it * KK + ip] + __ldg(feats + (b * TT + t) * KK + it);
        }
    }
#pragma unroll
    for (int o = 16; o > 0; o >>= 1) g += __shfl_xor_sync(0xffffffffu, g, o);
    if (w == 1 && lane == 0) gold_sh = g;

    __syncthreads();

    // ---- combine (forward warp): score = log(sum_j alpha_j * beta_j) + sF + sB ----
    if (w == 0) {
        float af, bf;
        {
            u16 ah = vfin[0][j];
            u16 bh = vfin[1][j];
            asm("cvt.f32.bf16 %0, %1;" : "=f"(af) : "h"(ah));
            asm("cvt.f32.bf16 %0, %1;" : "=f"(bf) : "h"(bh));
        }
        float prod = (lane < KK) ? af * bf : 0.0f;
#pragma unroll
        for (int o = 16; o > 0; o >>= 1) prod += __shfl_xor_sync(0xffffffffu, prod, o);
        float fwd = __logf(prod) + s + sc_sh;

        if (lane == 0) {
            double part = (double)fwd - (double)g - (double)gold_sh;
            atomicAdd(&g_sum, part);
            __threadfence();
            u32 old = atomicAdd(&g_ticket, 1u);
            if (old == (u32)(BATCH - 1)) {
                __threadfence();
                out[0] = (float)(g_sum * (1.0 / (double)BATCH));
                g_sum = 0.0;   // self-reset for next graph replay
                g_ticket = 0u;
            }
        }
    }
}

extern "C" void kernel_launch(void* const* d_in, const int* in_sizes, int n_in,
                              void* d_out, int out_size) {
    const float* feats = (const float*)d_in[0];
    const float* trans = (const float*)d_in[1];
    const void* tags = d_in[2];
    const int* startp = (const int*)d_in[3];

    crf_kernel<<<BATCH, 64>>>(feats, trans, tags, startp, (float*)d_out);
}

// round 17
// speedup vs baseline: 1.2258x; 1.2258x over previous
#include <cuda_runtime.h>
#include <cstdint>

#define KK 24
#define TT 512
#define BATCH 2048

// fused final-reduction state (self-resetting -> deterministic across replays)
__device__ double g_sum;
__device__ unsigned int g_ticket;

typedef unsigned int u32;
typedef unsigned short u16;

// ---- bf16x2 helpers ----
static __device__ __forceinline__ u32 bffma2(u32 a, u32 b, u32 c) {
    u32 d;
    asm("fma.rn.bf16x2 %0, %1, %2, %3;" : "=r"(d) : "r"(a), "r"(b), "r"(c));
    return d;
}
static __device__ __forceinline__ u32 bfmul2(u32 a, u32 b) {
    u32 d;
    asm("mul.rn.bf16x2 %0, %1, %2;" : "=r"(d) : "r"(a), "r"(b));
    return d;
}
static __device__ __forceinline__ u32 bfadd2(u32 a, u32 b) {
    u32 d;
    asm("add.rn.bf16x2 %0, %1, %2;" : "=r"(d) : "r"(a), "r"(b));
    return d;
}
static __device__ __forceinline__ u32 bfmax2(u32 a, u32 b) {
    u32 d;
    asm("max.bf16x2 %0, %1, %2;" : "=r"(d) : "r"(a), "r"(b));
    return d;
}
static __device__ __forceinline__ void bf2f(u32 v, float& lo, float& hi) {
    u16 l, h;
    asm("mov.b32 {%0, %1}, %2;" : "=h"(l), "=h"(h) : "r"(v));
    asm("cvt.f32.bf16 %0, %1;" : "=f"(lo) : "h"(l));
    asm("cvt.f32.bf16 %0, %1;" : "=f"(hi) : "h"(h));
}
static __device__ __forceinline__ u16 f2bf(float f) {
    u16 h;
    asm("cvt.rn.bf16.f32 %0, %1;" : "=h"(h) : "f"(f));
    return h;
}
// pack (lo, hi) floats -> bf16x2 (PTX: first src -> high half)
static __device__ __forceinline__ u32 pkbf(float lo, float hi) {
    u32 r;
    asm("cvt.rn.bf16x2.f32 %0, %1, %2;" : "=r"(r) : "f"(hi), "f"(lo));
    return r;
}
static __device__ __forceinline__ u32 swap16(u32 v) {
    u32 r;
    asm("prmt.b32 %0, %1, %1, 0x1032;" : "=r"(r) : "r"(v));
    return r;
}
// pinned global load: placement fixed (volatile) so the compiler cannot
// re-hoist window prefetches into one L1TEX-queue-flooding burst.
static __device__ __forceinline__ float ldg_pin(const float* p) {
    float v;
    asm volatile("ld.global.nc.f32 %0, [%1];" : "=f"(v) : "l"(p));
    return v;
}
// ordered shared ops (32-bit shared-window addresses)
static __device__ __forceinline__ uint4 lds128(u32 addr) {
    uint4 v;
    asm volatile("ld.shared.v4.b32 {%0,%1,%2,%3}, [%4];"
                 : "=r"(v.x), "=r"(v.y), "=r"(v.z), "=r"(v.w) : "r"(addr) : "memory");
    return v;
}
static __device__ __forceinline__ void sts16(u32 addr, u32 val) {
    asm volatile("st.shared.u16 [%0], %1;" :: "r"(addr), "r"(val) : "memory");
}
static __device__ __forceinline__ u32 smem_u32(const void* p) {
    u32 a;
    asm("{ .reg .u64 t; cvta.to.shared.u64 t, %1; cvt.u32.u64 %0, t; }" : "=r"(a) : "l"(p));
    return a;
}

// one recursion step, ONE batch, all-bf16 datapath, no warp barrier.
template <bool RN>
static __device__ __forceinline__ void step1(u32 src, u32 dst,
                                             const u32* __restrict__ E2,
                                             u32 fe2, float& s) {
    uint4 A = lds128(src), B = lds128(src + 16), C = lds128(src + 32);
    u32 q0 = A.x, q1 = A.y, q2 = A.z, q3 = A.w;
    u32 q4 = B.x, q5 = B.y, q6 = B.z, q7 = B.w;
    u32 q8 = C.x, q9 = C.y, q10 = C.z, q11 = C.w;

    u32 c0 = bfmul2(E2[0], q0);
    u32 c1 = bfmul2(E2[1], q1);
    u32 c2 = bfmul2(E2[2], q2);
    u32 c3 = bfmul2(E2[3], q3);
    c0 = bffma2(E2[4], q4, c0);
    c1 = bffma2(E2[5], q5, c1);
    c2 = bffma2(E2[6], q6, c2);
    c3 = bffma2(E2[7], q7, c3);
    c0 = bffma2(E2[8], q8, c0);
    c1 = bffma2(E2[9], q9, c1);
    c2 = bffma2(E2[10], q10, c2);
    c3 = bffma2(E2[11], q11, c3);
    u32 ct = bfadd2(bfadd2(c0, c1), bfadd2(c2, c3));
    u32 tot = bfadd2(ct, swap16(ct));  // both halves = lo+hi
    u32 vq = bfmul2(tot, fe2);

    if (RN) {
        u32 m0 = bfmax2(q0, q1), m1 = bfmax2(q2, q3), m2 = bfmax2(q4, q5);
        u32 m3 = bfmax2(q6, q7), m4 = bfmax2(q8, q9), m5 = bfmax2(q10, q11);
        m0 = bfmax2(bfmax2(m0, m1), bfmax2(m2, m3));
        m0 = bfmax2(m0, bfmax2(m4, m5));
        float ma, mb;
        bf2f(m0, ma, mb);
        float m = fmaxf(ma, mb);
        float inv = 1.0f / m;
        vq = bfmul2(vq, pkbf(inv, inv));
        s += __logf(m);
    }
    sts16(dst, vq);
}

#define STEP(SA, DA, RN, IDX) step1<RN>(SA, DA, E2, fe2[IDX], s)

// step + ONE pinned prefetch for next window (shallow L1TEX queue); DIR = +1 fwd, -1 bwd
#define STEPL(SA, DA, RN, IDX, DIR)                 \
    do {                                            \
        fn[IDX] = ldg_pin(p + (DIR) * (IDX) * KK);  \
        step1<RN>(SA, DA, E2, fe2[IDX], s);         \
    } while (0)

#define WIN8L(RN0, DIR)                 \
    STEPL(a0, d1, RN0, 0, DIR);         \
    STEPL(a1, d0, false, 1, DIR);       \
    STEPL(a0, d1, false, 2, DIR);       \
    STEPL(a1, d0, false, 3, DIR);       \
    STEPL(a0, d1, false, 4, DIR);       \
    STEPL(a1, d0, false, 5, DIR);       \
    STEPL(a0, d1, false, 6, DIR);       \
    STEPL(a1, d0, false, 7, DIR)

__global__ __launch_bounds__(64, 14) void crf_kernel(const float* __restrict__ feats,
                                                     const float* __restrict__ trans,
                                                     const void* __restrict__ tags,
                                                     const int* __restrict__ startp,
                                                     float* __restrict__ out) {
    __shared__ __align__(16) u16 vh[2][2][32];  // [warp][buf][state] bf16
    __shared__ float sc_sh;    // backward warp's scale sum
    __shared__ float gold_sh;  // backward warp's gold partial
    const int lane = threadIdx.x & 31;
    const int w = threadIdx.x >> 5;  // 0 = forward, 1 = backward
    const int b = blockIdx.x;
    const int j = (lane < KK) ? lane : (KK - 1);

    const int start = startp[0];  // low word valid for LE int32/int64

    const u32 sb = smem_u32(&vh[0][0][0]);
    const u32 a0 = sb + (w * 2 + 0) * 64;
    const u32 a1 = sb + (w * 2 + 1) * 64;
    const u32 d0 = a0 + lane * 2;
    const u32 d1 = a1 + lane * 2;

    // E2: fwd = row j of exp(trans), paired over i; bwd = column j (E^T)
    u32 E2[12];
    if (w == 0) {
#pragma unroll
        for (int k = 0; k < 12; ++k)
            E2[k] = pkbf(__expf(trans[j * KK + 2 * k]), __expf(trans[j * KK + 2 * k + 1]));
    } else {
#pragma unroll
        for (int k = 0; k < 12; ++k)
            E2[k] = pkbf(__expf(trans[(2 * k) * KK + j]), __expf(trans[(2 * k + 1) * KK + j]));
    }

    float s = 0.0f;
    const float* fb = feats + b * (TT * KK) + j;
    float fn[8];
    u32 fe2[8];

    if (w == 0) {
        // ---------------- forward: alpha, t = 1..256 (32 windows of 8) ----------------
        sts16(d0, (lane == start) ? 0x3F80u : 0u);  // bf16 1.0 / 0.0
#pragma unroll
        for (int r = 0; r < 8; ++r) fn[r] = __ldg(fb + (1 + r) * KK);
        __syncwarp();
#pragma unroll 1
        for (int wi = 0; wi < 32; ++wi) {
#pragma unroll
            for (int r = 0; r < 8; ++r) {
                float e = __expf(fn[r]);
                fe2[r] = pkbf(e, e);
            }
            const float* p = fb + (8 * (wi + 1) + 1) * KK;  // max base 257: in-bounds
            if (wi == 0) {
                WIN8L(false, 1);
            } else {
                WIN8L(true, 1);
            }
        }
        // alpha(256) in buffer 0
    } else {
        // -------- backward: s(t)=fe_t*beta(t), t = 511..257, then beta(256) ----------
#pragma unroll
        for (int r = 0; r < 7; ++r) fn[r] = __ldg(fb + (511 - r) * KK);
        float e0 = __expf(fn[0]);
#pragma unroll
        for (int r = 0; r < 7; ++r) {
            float e = (r == 0) ? e0 : __expf(fn[r]);
            fe2[r] = pkbf(e, e);
        }
        sts16(d0, (lane < KK) ? (u32)f2bf(e0) : 0u);  // s(511)
#pragma unroll
        for (int r = 0; r < 8; ++r) fn[r] = __ldg(fb + (504 - r) * KK);
        __syncwarp();
        // prologue: t = 510..505
        STEP(a0, d1, false, 1);
        STEP(a1, d0, false, 2);
        STEP(a0, d1, false, 3);
        STEP(a1, d0, false, 4);
        STEP(a0, d1, false, 5);
        STEP(a1, d0, false, 6);
        // 31 windows of 8: t = 504..257; next-window loads t = base-r, one per step
#pragma unroll 1
        for (int wi = 0; wi < 31; ++wi) {
#pragma unroll
            for (int r = 0; r < 8; ++r) {
                float e = __expf(fn[r]);
                fe2[r] = pkbf(e, e);
            }
            const float* p = fb + (504 - 8 * (wi + 1)) * KK;  // min base 256: in-bounds
            WIN8L(true, -1);
        }
        // final fe-free step: beta(256) = E^T s(257); buffer0 -> buffer1
        step1<false>(a0, d1, E2, 0x3F803F80u /* (1,1) */, s);
        __syncwarp();
        if (lane == 0) sc_sh = s;
        // beta(256) in buffer 1 of warp 1
    }

    // ---- gold score: warps split the t-range of batch b (exact fp32) ----
    const u32* wds = (const u32*)tags;
    u32 hiw = wds[2 * lane + 1];
    const int is64 = (__ballot_sync(0xffffffffu, hiw != 0u) == 0u);
    float g = 0.0f;
    if (is64) {
        const long long* tg = (const long long*)tags + b * TT;
#pragma unroll
        for (int t = 1 + lane + 32 * w; t < TT; t += 64) {
            int it = (int)tg[t], ip = (int)tg[t - 1];
            g += trans[it * KK + ip] + __ldg(feats + (b * TT + t) * KK + it);
        }
    } else {
        const int* tg = (const int*)tags + b * TT;
#pragma unroll
        for (int t = 1 + lane + 32 * w; t < TT; t += 64) {
            int it = tg[t], ip = tg[t - 1];
            g += trans[it * KK + ip] + __ldg(feats + (b * TT + t) * KK + it);
        }
    }
#pragma unroll
    for (int o = 16; o > 0; o >>= 1) g += __shfl_xor_sync(0xffffffffu, g, o);
    if (w == 1 && lane == 0) gold_sh = g;

    __syncthreads();

    // ---- combine (forward warp): score = log(sum_j alpha_j * beta_j) + sF + sB ----
    if (w == 0) {
        float af, bf;
        {
            u16 ah = vh[0][0][j];  // alpha(256): warp0 buffer0
            u16 bh = vh[1][1][j];  // beta(256):  warp1 buffer1
            asm("cvt.f32.bf16 %0, %1;" : "=f"(af) : "h"(ah));
            asm("cvt.f32.bf16 %0, %1;" : "=f"(bf) : "h"(bh));
        }
        float prod = (lane < KK) ? af * bf : 0.0f;
#pragma unroll
        for (int o = 16; o > 0; o >>= 1) prod += __shfl_xor_sync(0xffffffffu, prod, o);
        float fwd = __logf(prod) + s + sc_sh;

        if (lane == 0) {
            double part = (double)fwd - (double)g - (double)gold_sh;
            atomicAdd(&g_sum, part);
            __threadfence();
            u32 old = atomicAdd(&g_ticket, 1u);
            if (old == (u32)(BATCH - 1)) {
                __threadfence();
                out[0] = (float)(g_sum * (1.0 / (double)BATCH));
                g_sum = 0.0;   // self-reset for next graph replay
                g_ticket = 0u;
            }
        }
    }
}

extern "C" void kernel_launch(void* const* d_in, const int* in_sizes, int n_in,
                              void* d_out, int out_size) {
    const float* feats = (const float*)d_in[0];
    const float* trans = (const float*)d_in[1];
    const void* tags = d_in[2];
    const int* startp = (const int*)d_in[3];

    crf_kernel<<<BATCH, 64>>>(feats, trans, tags, startp, (float*)d_out);
}